// round 10
// baseline (speedup 1.0000x reference)
#include <cuda_runtime.h>
#include <cuda_bf16.h>
#include <cstdint>

#define MDIM 8192
#define KDIM 4096
#define NDIM 4096

#define TILE_M 128
#define TILE_N 256
#define ITERS_PER_TILE 64      // k-steps of 64 per tile
#define NTILES 1024            // 64 m-tiles x 16 n-tiles
#define GRIDX 148
#define THREADS 256
#define NWARPS (THREADS / 32)
#define NSLOTS 4

// Tile-major pre-swizzled scratch:
// g_xq: [mt(64)][ks(64)] tiles of 128x64 bf16, rows 128B, XOR-swizzled
// g_wq: [nt(16)][ks(64)] tiles of 256x64 bf16
__device__ __nv_bfloat16 g_xq[(size_t)MDIM * KDIM];
__device__ __nv_bfloat16 g_wq[(size_t)NDIM * KDIM];

#define A_TILE_BYTES 16384
#define B_TILE_BYTES 32768

// ---------------- helpers ----------------
__device__ __forceinline__ uint32_t smem_u32(const void* p) {
    uint32_t a;
    asm("{ .reg .u64 t; cvta.to.shared.u64 t, %1; cvt.u32.u64 %0, t; }" : "=r"(a) : "l"(p));
    return a;
}
__device__ __forceinline__ void ldm_x4(uint32_t* r, uint32_t addr) {
    asm volatile("ldmatrix.sync.aligned.m8n8.x4.shared.b16 {%0,%1,%2,%3}, [%4];"
                 : "=r"(r[0]), "=r"(r[1]), "=r"(r[2]), "=r"(r[3]) : "r"(addr));
}
__device__ __forceinline__ void mma_bf16(float* d, const uint32_t* a, const uint32_t* b) {
    asm volatile(
        "mma.sync.aligned.m16n8k16.row.col.f32.bf16.bf16.f32 "
        "{%0,%1,%2,%3}, {%4,%5,%6,%7}, {%8,%9}, {%0,%1,%2,%3};"
        : "+f"(d[0]), "+f"(d[1]), "+f"(d[2]), "+f"(d[3])
        : "r"(a[0]), "r"(a[1]), "r"(a[2]), "r"(a[3]), "r"(b[0]), "r"(b[1]));
}
__device__ __forceinline__ uint32_t pack_bf16(float a, float b) {
    __nv_bfloat162 t = __floats2bfloat162_rn(a, b);
    return *reinterpret_cast<uint32_t*>(&t);
}
__device__ __forceinline__ void bulk_ld(uint32_t dst, const void* src, uint32_t bytes,
                                        uint32_t mbar) {
    asm volatile(
        "cp.async.bulk.shared::cta.global.mbarrier::complete_tx::bytes [%0], [%1], %2, [%3];"
        :: "r"(dst), "l"(src), "r"(bytes), "r"(mbar) : "memory");
}
#define MBAR_INIT(addr, cnt) \
    asm volatile("mbarrier.init.shared.b64 [%0], %1;" :: "r"(addr), "r"(cnt) : "memory")
#define MBAR_EXPECT_TX(addr, bytes) \
    asm volatile("mbarrier.arrive.expect_tx.shared.b64 _, [%0], %1;" \
                 :: "r"(addr), "r"(bytes) : "memory")
#define MBAR_ARRIVE(addr) \
    asm volatile("mbarrier.arrive.release.cta.shared.b64 _, [%0];" :: "r"(addr) : "memory")
__device__ __forceinline__ void mbar_wait(uint32_t mbar, uint32_t parity) {
    asm volatile(
        "{\n\t"
        ".reg .pred P;\n\t"
        "WAIT_%=:\n\t"
        "mbarrier.try_wait.parity.acquire.cta.shared::cta.b64 P, [%0], %1, 0x989680;\n\t"
        "@P bra DONE_%=;\n\t"
        "bra WAIT_%=;\n\t"
        "DONE_%=:\n\t"
        "}" :: "r"(mbar), "r"(parity) : "memory");
}

// ---------------- fused prelude: quantize x + convert w, tile-major swizzled ------
__global__ void __launch_bounds__(256) prelude_kernel(const float* __restrict__ x,
                                                      const int* __restrict__ w,
                                                      const float* __restrict__ is_p,
                                                      const int* __restrict__ izp_p,
                                                      const int* __restrict__ wzp) {
    int b = blockIdx.x;
    if (b < 16384) {
        size_t base = ((size_t)b * 256 + threadIdx.x) * 8;
        float inv = 1.0f / is_p[0];
        float zp = (float)izp_p[0];
        float4 v0 = *(const float4*)(x + base);
        float4 v1 = *(const float4*)(x + base + 4);
        float q[8];
        q[0] = v0.x; q[1] = v0.y; q[2] = v0.z; q[3] = v0.w;
        q[4] = v1.x; q[5] = v1.y; q[6] = v1.z; q[7] = v1.w;
#pragma unroll
        for (int i = 0; i < 8; i++)
            q[i] = fminf(fmaxf(rintf(q[i] * inv) + zp, -128.f), 127.f) - zp;
        uint4 o;
        o.x = pack_bf16(q[0], q[1]);
        o.y = pack_bf16(q[2], q[3]);
        o.z = pack_bf16(q[4], q[5]);
        o.w = pack_bf16(q[6], q[7]);
        int m = (int)(base >> 12);
        int k = (int)(base & 4095);
        int mt = m >> 7, row = m & 127;
        int ks = k >> 6, u = (k & 63) >> 3;
        size_t dst = (size_t)(mt * 64 + ks) * A_TILE_BYTES +
                     row * 128 + ((u ^ (row & 7)) << 4);
        *reinterpret_cast<uint4*>(reinterpret_cast<char*>(g_xq) + dst) = o;
    } else {
        size_t base = ((size_t)(b - 16384) * 256 + threadIdx.x) * 8;
        int n = (int)(base >> 12);
        int k = (int)(base & 4095);
        int zp = wzp[n];
        int4 a = *(const int4*)(w + base);
        int4 c = *(const int4*)(w + base + 4);
        uint4 o;
        o.x = pack_bf16((float)(a.x - zp), (float)(a.y - zp));
        o.y = pack_bf16((float)(a.z - zp), (float)(a.w - zp));
        o.z = pack_bf16((float)(c.x - zp), (float)(c.y - zp));
        o.w = pack_bf16((float)(c.z - zp), (float)(c.w - zp));
        int nt = n >> 8, row = n & 255;
        int ks = k >> 6, u = (k & 63) >> 3;
        size_t dst = (size_t)(nt * 64 + ks) * B_TILE_BYTES +
                     row * 128 + ((u ^ (row & 7)) << 4);
        *reinterpret_cast<uint4*>(reinterpret_cast<char*>(g_wq) + dst) = o;
    }
}

// ---------------- persistent HMMA bf16 GEMM, 4-stage 48KB ring ----------------
// smem: [0,32) full mbars(4), [32,64) empty mbars(4), stages @4096
#define S_STAGE (A_TILE_BYTES + B_TILE_BYTES)   // 49152
#define S_BUF 4096
#define SMEM_BYTES (S_BUF + NSLOTS * S_STAGE)   // 200704

__device__ __forceinline__ void tile_coords(int t, int& mt, int& nt) {
    int g = t >> 7;          // group of 8 m-tiles x 16 n-tiles
    int r = t & 127;
    mt = g * 8 + (r & 7);
    nt = r >> 3;
}

__global__ void __launch_bounds__(THREADS, 1)
gemm_kernel(const float* __restrict__ wscale, const float* __restrict__ in_scale,
            const int* __restrict__ bias_int, const float* __restrict__ bias_scale,
            float* __restrict__ out) {
    extern __shared__ __align__(1024) char smem[];
    const uint32_t sbase = smem_u32(smem);
    const int tid = threadIdx.x;
    const int lane = tid & 31;
    const int wid = tid >> 5;
    const int warpM = wid >> 2;       // 2 -> 64 rows each
    const int warpN = wid & 3;        // 4 -> 64 cols each
    const int bid = blockIdx.x;

    const char* xbase = reinterpret_cast<const char*>(g_xq);
    const char* wbase = reinterpret_cast<const char*>(g_wq);

    if (tid == 0) {
#pragma unroll
        for (int s = 0; s < NSLOTS; s++) {
            MBAR_INIT(sbase + s * 8, 1);
            MBAR_INIT(sbase + 32 + s * 8, NWARPS);
        }
    }
    __syncthreads();

    const float is = in_scale[0];

    int t = bid;
    int mt, nt;
    tile_coords(t, mt, nt);

    // prologue: flat positions 0..2 in flight
    if (tid == 0) {
        const char* gA0 = xbase + (size_t)mt * 64 * A_TILE_BYTES;
        const char* gB0 = wbase + (size_t)nt * 64 * B_TILE_BYTES;
#pragma unroll
        for (int p = 0; p < 3; p++) {
            uint32_t fmb = sbase + p * 8;
            uint32_t dst = sbase + S_BUF + p * S_STAGE;
            MBAR_EXPECT_TX(fmb, S_STAGE);
            bulk_ld(dst, gA0 + (size_t)p * A_TILE_BYTES, A_TILE_BYTES, fmb);
            bulk_ld(dst + A_TILE_BYTES, gB0 + (size_t)p * B_TILE_BYTES, B_TILE_BYTES, fmb);
        }
    }

    float acc[4][8][4];
#pragma unroll
    for (int i = 0; i < 4; i++)
#pragma unroll
        for (int j = 0; j < 8; j++)
#pragma unroll
            for (int q = 0; q < 4; q++) acc[i][j][q] = 0.0f;

    // ldmatrix lane-address components (swizzled rows of 128B)
    const int a_row = lane & 15;
    const int a_kh = (lane >> 4) & 1;
    const int b_noff = (lane & 7) + ((lane & 16) >> 1);
    const int b_kh = (lane >> 3) & 1;

    int rA[4], rB[4];
#pragma unroll
    for (int mi = 0; mi < 4; mi++) rA[mi] = warpM * 64 + mi * 16 + a_row;
#pragma unroll
    for (int np = 0; np < 4; np++) rB[np] = warpN * 64 + np * 16 + b_noff;

    uint32_t git = 0;   // flat small-iteration counter

    while (true) {
#pragma unroll 1
        for (int it = 0; it < ITERS_PER_TILE; it++, git++) {
            // rotating producer: warp (git & 7) issues the load for position git+3
            if (wid == (int)(git & 7) && lane == 0) {
                uint32_t pgit = git + 3;
                int pt = bid + GRIDX * (int)(pgit >> 6);
                if (pt < NTILES) {
                    int pit = (int)(pgit & 63);
                    int pmt, pnt;
                    tile_coords(pt, pmt, pnt);
                    uint32_t s = pgit & (NSLOTS - 1);
                    uint32_t j = pgit >> 2;
                    uint32_t emb = sbase + 32 + s * 8;
                    uint32_t fmb = sbase + s * 8;
                    if (j > 0) mbar_wait(emb, (j - 1) & 1);
                    MBAR_EXPECT_TX(fmb, S_STAGE);
                    uint32_t dst = sbase + S_BUF + s * S_STAGE;
                    bulk_ld(dst, xbase + (size_t)(pmt * 64 + pit) * A_TILE_BYTES,
                            A_TILE_BYTES, fmb);
                    bulk_ld(dst + A_TILE_BYTES,
                            wbase + (size_t)(pnt * 64 + pit) * B_TILE_BYTES,
                            B_TILE_BYTES, fmb);
                }
            }

            uint32_t slot = git & (NSLOTS - 1);
            mbar_wait(sbase + slot * 8, (git >> 2) & 1);

            uint32_t sA = sbase + S_BUF + slot * S_STAGE;
            uint32_t sB = sA + A_TILE_BYTES;

#pragma unroll
            for (int ks = 0; ks < 4; ks++) {   // four k=16 steps
                uint32_t a[4][4], b[4][4];
                int uA = ks * 2 + a_kh;
                int uB = ks * 2 + b_kh;
#pragma unroll
                for (int mi = 0; mi < 4; mi++)
                    ldm_x4(a[mi], sA + rA[mi] * 128 + ((uA ^ (rA[mi] & 7)) << 4));
#pragma unroll
                for (int np = 0; np < 4; np++)
                    ldm_x4(b[np], sB + rB[np] * 128 + ((uB ^ (rB[np] & 7)) << 4));
#pragma unroll
                for (int mi = 0; mi < 4; mi++)
#pragma unroll
                    for (int ni = 0; ni < 8; ni++)
                        mma_bf16(acc[mi][ni], a[mi], &b[ni >> 1][(ni & 1) * 2]);
            }

            if (lane == 0) MBAR_ARRIVE(sbase + 32 + slot * 8);
        }

        // epilogue for tile t (next tile's first stages already in flight)
        {
            const int m0 = mt * TILE_M;
            const int n0 = nt * TILE_N;
            const int gid = lane >> 2, tig = lane & 3;
#pragma unroll
            for (int ni = 0; ni < 8; ni++) {
                int n = n0 + warpN * 64 + ni * 8 + tig * 2;
                float al0 = is * wscale[n];
                float al1 = is * wscale[n + 1];
                float be0 = (float)bias_int[n] * bias_scale[n];
                float be1 = (float)bias_int[n + 1] * bias_scale[n + 1];
#pragma unroll
                for (int mi = 0; mi < 4; mi++) {
                    size_t r = (size_t)m0 + warpM * 64 + mi * 16 + gid;
                    float2 v0 = {acc[mi][ni][0] * al0 + be0, acc[mi][ni][1] * al1 + be1};
                    float2 v1 = {acc[mi][ni][2] * al0 + be0, acc[mi][ni][3] * al1 + be1};
                    *reinterpret_cast<float2*>(out + r * NDIM + n) = v0;
                    *reinterpret_cast<float2*>(out + (r + 8) * NDIM + n) = v1;
                    acc[mi][ni][0] = 0.0f; acc[mi][ni][1] = 0.0f;
                    acc[mi][ni][2] = 0.0f; acc[mi][ni][3] = 0.0f;
                }
            }
        }

        t += GRIDX;
        if (t >= NTILES) break;
        tile_coords(t, mt, nt);
    }
}

// ---------------- launch ----------------
extern "C" void kernel_launch(void* const* d_in, const int* in_sizes, int n_in,
                              void* d_out, int out_size) {
    const float* x = (const float*)d_in[0];
    const int* w = (const int*)d_in[1];
    const float* wsc = (const float*)d_in[2];
    const int* wzp = (const int*)d_in[3];
    const float* isc = (const float*)d_in[4];
    const int* izp = (const int*)d_in[5];
    const int* bi = (const int*)d_in[6];
    const float* bsc = (const float*)d_in[7];
    float* out = (float*)d_out;

    cudaFuncSetAttribute(gemm_kernel, cudaFuncAttributeMaxDynamicSharedMemorySize,
                         SMEM_BYTES);

    prelude_kernel<<<16384 + 8192, 256>>>(x, w, isc, izp, wzp);
    gemm_kernel<<<GRIDX, THREADS, SMEM_BYTES>>>(wsc, isc, bi, bsc, out);
}